// round 1
// baseline (speedup 1.0000x reference)
#include <cuda_runtime.h>
#include <math_constants.h>

#define B_ 4
#define S_ 512
#define D_ 768
#define MAX_LEN_ 10
#define LEN_EMB_ 25
#define NUM_LABELS_ 9
#define N_ (S_ * MAX_LEN_)   // 5120

// Precomputed length-logits table: len_logits[L-1][c] = len_emb_table[L-1] . W[768:, c] + b[c]
__device__ float g_len_logits[MAX_LEN_ * NUM_LABELS_];

__global__ void len_logits_kernel(const float* __restrict__ len_emb_table,
                                  const float* __restrict__ W,
                                  const float* __restrict__ bvec) {
    int i = threadIdx.x;
    if (i < MAX_LEN_ * NUM_LABELS_) {
        int L = i / NUM_LABELS_;
        int c = i % NUM_LABELS_;
        float s = bvec[c];
        #pragma unroll
        for (int k = 0; k < LEN_EMB_; k++) {
            s = fmaf(len_emb_table[L * LEN_EMB_ + k], W[(D_ + k) * NUM_LABELS_ + c], s);
        }
        g_len_logits[i] = s;
    }
}

__device__ __forceinline__ float4 max4(float4 a, float4 b) {
    float4 r;
    r.x = fmaxf(a.x, b.x);
    r.y = fmaxf(a.y, b.y);
    r.z = fmaxf(a.z, b.z);
    r.w = fmaxf(a.w, b.w);
    return r;
}

// One warp per (batch, start, column-triple) task.
// Lane owns d = 4*(lane + 32*k) + q for k in [0,6), q in [0,4)  (768 = 32*24 elems/warp).
// W slice for the 3 owned columns lives in registers (72 floats/lane).
__global__ __launch_bounds__(128) void span_ner_kernel(
    const float* __restrict__ we,       // [B, S, D]
    const int*   __restrict__ starts,   // [B, N]
    const int*   __restrict__ lens,     // [B, N]
    const float* __restrict__ W,        // [D+LEN_EMB, 9]
    float*       __restrict__ out)      // [B, N, 9]
{
    const int lane = threadIdx.x & 31;
    const int warp_global = blockIdx.x * 4 + (threadIdx.x >> 5);
    // csplit fastest -> consecutive warps share (b, s) rows in L1
    const int csplit = warp_global % 3;
    const int bs = warp_global / 3;
    if (bs >= B_ * S_) return;
    const int b = bs / S_;
    const int s = bs % S_;
    const int c0 = csplit * 3;

    // Load this lane's W slice into registers: Wr[k][q][t]
    float Wr[6][4][3];
    #pragma unroll
    for (int k = 0; k < 6; k++) {
        #pragma unroll
        for (int q = 0; q < 4; q++) {
            const int d = 4 * (lane + 32 * k) + q;
            const float* wp = W + (size_t)d * NUM_LABELS_ + c0;
            Wr[k][q][0] = wp[0];
            Wr[k][q][1] = wp[1];
            Wr[k][q][2] = wp[2];
        }
    }

    const int n0 = s * MAX_LEN_;
    const size_t bn = (size_t)b * N_ + n0;
    const int start = starts[bn];
    const int* lensp = lens + bn;

    float4 m[6];
    #pragma unroll
    for (int k = 0; k < 6; k++) m[k] = make_float4(-CUDART_INF_F, -CUDART_INF_F, -CUDART_INF_F, -CUDART_INF_F);

    int covered = 0;
    #pragma unroll
    for (int j = 0; j < MAX_LEN_; j++) {
        const int L = lensp[j];   // uniform across warp; nondecreasing in j
        while (covered < L) {
            const float4* row = (const float4*)(we + ((size_t)b * S_ + start + covered) * D_);
            #pragma unroll
            for (int k = 0; k < 6; k++) {
                float4 v = row[lane + 32 * k];
                m[k] = max4(m[k], v);
            }
            covered++;
        }

        // partial dot: 24 elems x 3 columns
        float a0 = 0.f, a1 = 0.f, a2 = 0.f;
        #pragma unroll
        for (int k = 0; k < 6; k++) {
            a0 = fmaf(m[k].x, Wr[k][0][0], a0); a1 = fmaf(m[k].x, Wr[k][0][1], a1); a2 = fmaf(m[k].x, Wr[k][0][2], a2);
            a0 = fmaf(m[k].y, Wr[k][1][0], a0); a1 = fmaf(m[k].y, Wr[k][1][1], a1); a2 = fmaf(m[k].y, Wr[k][1][2], a2);
            a0 = fmaf(m[k].z, Wr[k][2][0], a0); a1 = fmaf(m[k].z, Wr[k][2][1], a1); a2 = fmaf(m[k].z, Wr[k][2][2], a2);
            a0 = fmaf(m[k].w, Wr[k][3][0], a0); a1 = fmaf(m[k].w, Wr[k][3][1], a1); a2 = fmaf(m[k].w, Wr[k][3][2], a2);
        }

        // warp butterfly reduce (all lanes end with the full sums)
        #pragma unroll
        for (int off = 16; off > 0; off >>= 1) {
            a0 += __shfl_xor_sync(0xFFFFFFFFu, a0, off);
            a1 += __shfl_xor_sync(0xFFFFFFFFu, a1, off);
            a2 += __shfl_xor_sync(0xFFFFFFFFu, a2, off);
        }

        if (lane < 3) {
            const float av = (lane == 0) ? a0 : ((lane == 1) ? a1 : a2);
            const int c = c0 + lane;
            out[(bn + j) * NUM_LABELS_ + c] = av + g_len_logits[(L - 1) * NUM_LABELS_ + c];
        }
    }
}

extern "C" void kernel_launch(void* const* d_in, const int* in_sizes, int n_in,
                              void* d_out, int out_size) {
    const float* we     = (const float*)d_in[0];   // word_embeddings [B,S,D]
    const int*   starts = (const int*)d_in[1];     // span_starts [B,N]
    const int*   lens   = (const int*)d_in[2];     // span_lens [B,N]
    const float* let    = (const float*)d_in[3];   // len_emb_table [MAX_LEN, LEN_EMB]
    const float* W      = (const float*)d_in[4];   // W [D+LEN_EMB, 9]
    const float* bvec   = (const float*)d_in[5];   // b [9]
    float* out = (float*)d_out;

    len_logits_kernel<<<1, 96>>>(let, W, bvec);

    const int total_warps = B_ * S_ * 3;           // 6144 tasks
    const int blocks = (total_warps + 3) / 4;      // 4 warps/block, 128 threads
    span_ner_kernel<<<blocks, 128>>>(we, starts, lens, W, out);
}